// round 5
// baseline (speedup 1.0000x reference)
#include <cuda_runtime.h>
#include <cstdint>

// Problem constants
#define B_ 4
#define T_ 2048
#define C_ 2048
#define H_ 16
#define D_ 128

// Scratch (device globals: allocation-free per harness rules)
__device__ float g_Q[(size_t)B_ * H_ * T_ * D_];     // [B,H,T,Dh]  (tf32-rounded)
__device__ float g_K[(size_t)B_ * H_ * T_ * D_];
__device__ float g_V[(size_t)B_ * H_ * T_ * D_];
__device__ float g_ATT[(size_t)B_ * T_ * C_];        // [B,T,C] (tf32-rounded)
__device__ float g_xr[(size_t)B_ * T_ * C_];         // rounded x
__device__ float g_wqkv[(size_t)3 * C_ * C_];        // rounded qkv_w
__device__ float g_wproj[(size_t)C_ * C_];           // rounded proj_w

// ---------------------------------------------------------------------------
// Helpers (sm_80-class PTX only — safe on base sm_103 target)
// ---------------------------------------------------------------------------
__device__ __forceinline__ uint32_t smem_u32(const void* p) {
    uint32_t a;
    asm("{ .reg .u64 t; cvta.to.shared.u64 t, %1; cvt.u32.u64 %0, t; }"
        : "=r"(a) : "l"(p));
    return a;
}
__device__ __forceinline__ void cpa16(uint32_t dst, const void* src) {
    asm volatile("cp.async.cg.shared.global [%0], [%1], 16;"
                 :: "r"(dst), "l"(src));
}
#define CP_COMMIT() asm volatile("cp.async.commit_group;" ::: "memory")
#define CP_WAIT(n)  asm volatile("cp.async.wait_group " #n ";" ::: "memory")

__device__ __forceinline__ float rnd_tf32(float x) {
    uint32_t u;
    asm("cvt.rna.tf32.f32 %0, %1;" : "=r"(u) : "f"(x));
    return __uint_as_float(u);
}
__device__ __forceinline__ float4 rnd4(float4 v) {
    v.x = rnd_tf32(v.x); v.y = rnd_tf32(v.y);
    v.z = rnd_tf32(v.z); v.w = rnd_tf32(v.w);
    return v;
}

// D(16x8,f32) += A(16x8,tf32) * B(8x8,tf32)
__device__ __forceinline__ void mma16n8k8(float c[4], const uint32_t a[4],
                                          const uint32_t b[2]) {
    asm volatile(
        "mma.sync.aligned.m16n8k8.row.col.f32.tf32.tf32.f32 "
        "{%0,%1,%2,%3}, {%4,%5,%6,%7}, {%8,%9}, {%0,%1,%2,%3};"
        : "+f"(c[0]), "+f"(c[1]), "+f"(c[2]), "+f"(c[3])
        : "r"(a[0]), "r"(a[1]), "r"(a[2]), "r"(a[3]), "r"(b[0]), "r"(b[1]));
}

// ---------------------------------------------------------------------------
// Prep: tf32-round copy (one pass per matrix)
// ---------------------------------------------------------------------------
__global__ void rnd_prep(const float4* __restrict__ src, int which, int n4)
{
    float4* dst = (which == 0) ? (float4*)g_xr
                : (which == 1) ? (float4*)g_wqkv : (float4*)g_wproj;
    int i = blockIdx.x * blockDim.x + threadIdx.x;
    if (i < n4) dst[i] = rnd4(src[i]);
}

// ===========================================================================
// tf32 GEMM: C[M,N] = A[M,2048] @ W[N,2048]^T + bias[N]
// CTA 256x128, 512 threads / 16 warps (4m x 4n) at 64x32 each.
// BK=32, 3-stage cp.async pipeline. ~115 regs -> full 16-warp residency.
// mode 0: A=g_xr, W=g_wqkv, scatter (rounded) into g_Q/g_K/g_V.
// mode 1: A=g_ATT, W=g_wproj, row-major fp32 into Out.
// ===========================================================================
#define GSROW 36
#define GA_STG (256 * GSROW)            // 9216 floats
#define GB_STG (128 * GSROW)            // 4608 floats
#define GEMM_SMEM (3 * (GA_STG + GB_STG) * 4)   // 165888 bytes

__global__ void __launch_bounds__(512, 1)
gemm_mma(const float* __restrict__ bias, float* __restrict__ Out, int mode)
{
    extern __shared__ float sf[];
    const float* A = (mode == 0) ? g_xr : g_ATT;
    const float* W = (mode == 0) ? g_wqkv : g_wproj;
    const int K = C_;

    uint32_t sbase = smem_u32(sf);
    uint32_t a_sm = sbase;
    uint32_t b_sm = sbase + 3 * GA_STG * 4;

    int tid  = threadIdx.x;
    int lane = tid & 31;
    int warp = tid >> 5;                 // 0..15
    int g    = lane >> 2;
    int tig  = lane & 3;
    int wm   = warp >> 2;                // 0..3  (64 rows each)
    int wn   = warp & 3;                 // 0..3  (32 cols each)
    int bm   = blockIdx.y << 8;
    int bn   = blockIdx.x << 7;

    // cp.async: chunk id = tid + 512*s ; row = id>>3, c4 = id&7
    int crow = tid >> 3;                 // 0..63
    int cc4  = tid & 7;                  // 0..7
    const char* a_src0 = (const char*)(A + (size_t)(bm + crow) * K + (cc4 << 2));
    const char* b_src0 = (const char*)(W + (size_t)(bn + crow) * K + (cc4 << 2));
    uint32_t stg_off = (uint32_t)((crow * GSROW + (cc4 << 2)) * 4);

    float acc[4][4][4];
#pragma unroll
    for (int i = 0; i < 4; i++)
#pragma unroll
        for (int j = 0; j < 4; j++)
#pragma unroll
            for (int r = 0; r < 4; r++) acc[i][j][r] = 0.f;

    // ---- pipeline prologue: stages 0,1 ----
#pragma unroll
    for (int st = 0; st < 2; st++) {
        const char* asrc = a_src0 + (size_t)st * 128;   // 32 floats per kt
        const char* bsrc = b_src0 + (size_t)st * 128;
        uint32_t ad = a_sm + st * GA_STG * 4 + stg_off;
        uint32_t bd = b_sm + st * GB_STG * 4 + stg_off;
#pragma unroll
        for (int s = 0; s < 4; s++)      // A: 256 rows, 64 per step
            cpa16(ad + s * (64 * GSROW * 4), asrc + (size_t)s * 64 * K * 4);
#pragma unroll
        for (int s = 0; s < 2; s++)      // B: 128 rows
            cpa16(bd + s * (64 * GSROW * 4), bsrc + (size_t)s * 64 * K * 4);
        CP_COMMIT();
    }

    const int NKT = 64;
    for (int kt = 0; kt < NKT; kt++) {
        if (kt < NKT - 2) { CP_WAIT(1); } else { CP_WAIT(0); }
        __syncthreads();

        if (kt + 2 < NKT) {
            int st = kt + 2;
            int buf = st - (st / 3) * 3;
            const char* asrc = a_src0 + (size_t)st * 128;
            const char* bsrc = b_src0 + (size_t)st * 128;
            uint32_t ad = a_sm + buf * GA_STG * 4 + stg_off;
            uint32_t bd = b_sm + buf * GB_STG * 4 + stg_off;
#pragma unroll
            for (int s = 0; s < 4; s++)
                cpa16(ad + s * (64 * GSROW * 4), asrc + (size_t)s * 64 * K * 4);
#pragma unroll
            for (int s = 0; s < 2; s++)
                cpa16(bd + s * (64 * GSROW * 4), bsrc + (size_t)s * 64 * K * 4);
            CP_COMMIT();
        }

        int buf = kt - (kt / 3) * 3;
        const float* Ab = sf + buf * GA_STG;
        const float* Bb = sf + 3 * GA_STG + buf * GB_STG;

#pragma unroll
        for (int ks = 0; ks < 4; ks++) {
            int k0 = (ks << 3) + tig;
            uint32_t af[4][4], bf[4][2];
#pragma unroll
            for (int ma = 0; ma < 4; ma++) {
                int r = ((wm << 6) + (ma << 4) + g) * GSROW + k0;
                af[ma][0] = __float_as_uint(Ab[r]);
                af[ma][1] = __float_as_uint(Ab[r + 8 * GSROW]);
                af[ma][2] = __float_as_uint(Ab[r + 4]);
                af[ma][3] = __float_as_uint(Ab[r + 8 * GSROW + 4]);
            }
#pragma unroll
            for (int na = 0; na < 4; na++) {
                int r = ((wn << 5) + (na << 3) + g) * GSROW + k0;
                bf[na][0] = __float_as_uint(Bb[r]);
                bf[na][1] = __float_as_uint(Bb[r + 4]);
            }
#pragma unroll
            for (int ma = 0; ma < 4; ma++)
#pragma unroll
                for (int na = 0; na < 4; na++)
                    mma16n8k8(acc[ma][na], af[ma], bf[na]);
        }
    }

    // ---- epilogue ----
    int sel = blockIdx.x >> 4;           // mode 0 decode (N-tile = one slice)
    int hh  = blockIdx.x & 15;
    float* qkv_dst = (sel == 0) ? g_Q : ((sel == 1) ? g_K : g_V);

#pragma unroll
    for (int ma = 0; ma < 4; ma++) {
        int r0 = bm + (wm << 6) + (ma << 4) + g;
#pragma unroll
        for (int na = 0; na < 4; na++) {
            int cb = (wn << 5) + (na << 3) + (tig << 1);
            int nglob = bn + cb;
            float b0 = __ldg(bias + nglob);
            float b1 = __ldg(bias + nglob + 1);
            if (mode == 0) {
                float2 v0 = make_float2(rnd_tf32(acc[ma][na][0] + b0),
                                        rnd_tf32(acc[ma][na][1] + b1));
                float2 v1 = make_float2(rnd_tf32(acc[ma][na][2] + b0),
                                        rnd_tf32(acc[ma][na][3] + b1));
                int bb0 = r0 >> 11, t0 = r0 & 2047;
                int r1 = r0 + 8;
                int bb1 = r1 >> 11, t1 = r1 & 2047;
                *(float2*)(qkv_dst + (((size_t)(bb0 * H_ + hh)) * T_ + t0) * D_ + cb) = v0;
                *(float2*)(qkv_dst + (((size_t)(bb1 * H_ + hh)) * T_ + t1) * D_ + cb) = v1;
            } else {
                float2 v0 = make_float2(acc[ma][na][0] + b0, acc[ma][na][1] + b1);
                float2 v1 = make_float2(acc[ma][na][2] + b0, acc[ma][na][3] + b1);
                *(float2*)(Out + (size_t)r0 * C_ + nglob)       = v0;
                *(float2*)(Out + (size_t)(r0 + 8) * C_ + nglob) = v1;
            }
        }
    }
}

// ===========================================================================
// Flash attention on mma.sync tf32 — unchanged from Round-4 passing version.
// ===========================================================================
#define AROW 132
#define ATT_SMEM ((3 * 128 * AROW + 2 * 4 * 128) * 4)   // 206848 bytes

__global__ void __launch_bounds__(256, 1)
attn_mma()
{
    extern __shared__ float sf[];
    float* Qs   = sf;                        // [128][132]
    float* Ks   = sf + 128 * AROW;           // [128][132]  (aliased by P)
    float* Vs   = sf + 2 * 128 * AROW;       // [128][132]
    float* redm = sf + 3 * 128 * AROW;       // [4][128]
    float* reds = redm + 4 * 128;            // [4][128]

    uint32_t sbase = smem_u32(sf);
    uint32_t q_sm = sbase;
    uint32_t k_sm = sbase + 128 * AROW * 4;
    uint32_t v_sm = sbase + 2 * 128 * AROW * 4;

    int tid  = threadIdx.x;
    int lane = tid & 31;
    int warp = tid >> 5;
    int g    = lane >> 2;
    int tig  = lane & 3;
    int wm2  = warp >> 2;
    int wq   = warp & 3;

    int qb = (int)gridDim.x - 1 - (int)blockIdx.x;   // heavy blocks first
    int bh = blockIdx.y;
    size_t bhoff = (size_t)bh * T_ * D_;

    int crow = tid >> 5;
    int cc4  = tid & 31;
    uint32_t dst_off = (uint32_t)((crow * AROW + (cc4 << 2)) * 4);
    size_t   src_off = (size_t)crow * D_ + (cc4 << 2);

    {
        const float* qsrc = g_Q + bhoff + (size_t)qb * 128 * D_ + src_off;
#pragma unroll
        for (int s = 0; s < 16; s++)
            cpa16(q_sm + dst_off + s * (8 * AROW * 4), qsrc + (size_t)s * 8 * D_);
        CP_COMMIT();
    }

    float oacc[4][4][4];
#pragma unroll
    for (int i = 0; i < 4; i++)
#pragma unroll
        for (int j = 0; j < 4; j++)
#pragma unroll
            for (int r = 0; r < 4; r++) oacc[i][j][r] = 0.f;
    float m_i[8], l_i[8];
#pragma unroll
    for (int r = 0; r < 8; r++) { m_i[r] = -1.0e30f; l_i[r] = 0.f; }

    const float scale = 0.088388347648318447f;

    for (int kb = 0; kb <= qb; kb++) {
        __syncthreads();
        {
            const float* ksrc = g_K + bhoff + (size_t)kb * 128 * D_ + src_off;
            const float* vsrc = g_V + bhoff + (size_t)kb * 128 * D_ + src_off;
#pragma unroll
            for (int s = 0; s < 16; s++)
                cpa16(k_sm + dst_off + s * (8 * AROW * 4), ksrc + (size_t)s * 8 * D_);
#pragma unroll
            for (int s = 0; s < 16; s++)
                cpa16(v_sm + dst_off + s * (8 * AROW * 4), vsrc + (size_t)s * 8 * D_);
            CP_COMMIT();
        }
        CP_WAIT(0);
        __syncthreads();

        float sacc[4][4][4];
#pragma unroll
        for (int i = 0; i < 4; i++)
#pragma unroll
            for (int j = 0; j < 4; j++)
#pragma unroll
                for (int r = 0; r < 4; r++) sacc[i][j][r] = 0.f;

#pragma unroll
        for (int ks = 0; ks < 16; ks++) {
            int k0 = (ks << 3) + tig;
            uint32_t af[4][4], bf[4][2];
#pragma unroll
            for (int ma = 0; ma < 4; ma++) {
                int r = ((wm2 << 6) + (ma << 4) + g) * AROW + k0;
                af[ma][0] = __float_as_uint(Qs[r]);
                af[ma][1] = __float_as_uint(Qs[r + 8 * AROW]);
                af[ma][2] = __float_as_uint(Qs[r + 4]);
                af[ma][3] = __float_as_uint(Qs[r + 8 * AROW + 4]);
            }
#pragma unroll
            for (int na = 0; na < 4; na++) {
                int r = ((wq << 5) + (na << 3) + g) * AROW + k0;
                bf[na][0] = __float_as_uint(Ks[r]);
                bf[na][1] = __float_as_uint(Ks[r + 4]);
            }
#pragma unroll
            for (int ma = 0; ma < 4; ma++)
#pragma unroll
                for (int na = 0; na < 4; na++)
                    mma16n8k8(sacc[ma][na], af[ma], bf[na]);
        }

        bool diag = (kb == qb);
        float rmax[8];
#pragma unroll
        for (int r = 0; r < 8; r++) rmax[r] = -1.0e30f;
#pragma unroll
        for (int ma = 0; ma < 4; ma++)
#pragma unroll
            for (int h = 0; h < 2; h++) {
                int row_l = (wm2 << 6) + (ma << 4) + g + (h << 3);
                int ri = (ma << 1) + h;
#pragma unroll
                for (int na = 0; na < 4; na++)
#pragma unroll
                    for (int e = 0; e < 2; e++) {
                        int col_l = (wq << 5) + (na << 3) + (tig << 1) + e;
                        float s = sacc[ma][na][(h << 1) + e] * scale;
                        if (diag && col_l > row_l) s = -1.0e30f;
                        sacc[ma][na][(h << 1) + e] = s;
                        rmax[ri] = fmaxf(rmax[ri], s);
                    }
            }
#pragma unroll
        for (int r = 0; r < 8; r++) {
            rmax[r] = fmaxf(rmax[r], __shfl_xor_sync(0xffffffffu, rmax[r], 1));
            rmax[r] = fmaxf(rmax[r], __shfl_xor_sync(0xffffffffu, rmax[r], 2));
        }
        if (tig == 0) {
#pragma unroll
            for (int ma = 0; ma < 4; ma++)
#pragma unroll
                for (int h = 0; h < 2; h++)
                    redm[(wq << 7) + (wm2 << 6) + (ma << 4) + g + (h << 3)] =
                        rmax[(ma << 1) + h];
        }
        __syncthreads();

        float alpha[8], mnew[8], rsum[8];
#pragma unroll
        for (int ma = 0; ma < 4; ma++)
#pragma unroll
            for (int h = 0; h < 2; h++) {
                int row_l = (wm2 << 6) + (ma << 4) + g + (h << 3);
                int ri = (ma << 1) + h;
                float m4 = fmaxf(fmaxf(redm[row_l], redm[128 + row_l]),
                                 fmaxf(redm[256 + row_l], redm[384 + row_l]));
                mnew[ri] = fmaxf(m_i[ri], m4);
                alpha[ri] = __expf(m_i[ri] - mnew[ri]);
                m_i[ri] = mnew[ri];
                rsum[ri] = 0.f;
            }
#pragma unroll
        for (int ma = 0; ma < 4; ma++)
#pragma unroll
            for (int h = 0; h < 2; h++) {
                int ri = (ma << 1) + h;
                int row_l = (wm2 << 6) + (ma << 4) + g + (h << 3);
                float* prow = Ks + row_l * AROW + (wq << 5);
#pragma unroll
                for (int na = 0; na < 4; na++) {
                    float p0 = rnd_tf32(__expf(sacc[ma][na][(h << 1) + 0] - mnew[ri]));
                    float p1 = rnd_tf32(__expf(sacc[ma][na][(h << 1) + 1] - mnew[ri]));
                    rsum[ri] += p0 + p1;
                    *(float2*)(prow + (na << 3) + (tig << 1)) = make_float2(p0, p1);
                }
            }
#pragma unroll
        for (int r = 0; r < 8; r++) {
            rsum[r] += __shfl_xor_sync(0xffffffffu, rsum[r], 1);
            rsum[r] += __shfl_xor_sync(0xffffffffu, rsum[r], 2);
        }
        if (tig == 0) {
#pragma unroll
            for (int ma = 0; ma < 4; ma++)
#pragma unroll
                for (int h = 0; h < 2; h++)
                    reds[(wq << 7) + (wm2 << 6) + (ma << 4) + g + (h << 3)] =
                        rsum[(ma << 1) + h];
        }
        __syncthreads();

#pragma unroll
        for (int ma = 0; ma < 4; ma++)
#pragma unroll
            for (int h = 0; h < 2; h++) {
                int row_l = (wm2 << 6) + (ma << 4) + g + (h << 3);
                int ri = (ma << 1) + h;
                float ls = reds[row_l] + reds[128 + row_l] +
                           reds[256 + row_l] + reds[384 + row_l];
                l_i[ri] = l_i[ri] * alpha[ri] + ls;
            }
#pragma unroll
        for (int ma = 0; ma < 4; ma++)
#pragma unroll
            for (int na = 0; na < 4; na++) {
                oacc[ma][na][0] *= alpha[(ma << 1)];
                oacc[ma][na][1] *= alpha[(ma << 1)];
                oacc[ma][na][2] *= alpha[(ma << 1) + 1];
                oacc[ma][na][3] *= alpha[(ma << 1) + 1];
            }

#pragma unroll
        for (int ks = 0; ks < 16; ks++) {
            int k0 = (ks << 3) + tig;
            uint32_t af[4][4], bf[4][2];
#pragma unroll
            for (int ma = 0; ma < 4; ma++) {
                int r = ((wm2 << 6) + (ma << 4) + g) * AROW + k0;
                af[ma][0] = __float_as_uint(Ks[r]);
                af[ma][1] = __float_as_uint(Ks[r + 8 * AROW]);
                af[ma][2] = __float_as_uint(Ks[r + 4]);
                af[ma][3] = __float_as_uint(Ks[r + 8 * AROW + 4]);
            }
#pragma unroll
            for (int na = 0; na < 4; na++) {
                int d = (wq << 5) + (na << 3) + g;
                bf[na][0] = __float_as_uint(Vs[k0 * AROW + d]);
                bf[na][1] = __float_as_uint(Vs[(k0 + 4) * AROW + d]);
            }
#pragma unroll
            for (int ma = 0; ma < 4; ma++)
#pragma unroll
                for (int na = 0; na < 4; na++)
                    mma16n8k8(oacc[ma][na], af[ma], bf[na]);
        }
    }

    int b  = bh >> 4;
    int hh = bh & 15;
#pragma unroll
    for (int ma = 0; ma < 4; ma++)
#pragma unroll
        for (int h = 0; h < 2; h++) {
            int row_l = (wm2 << 6) + (ma << 4) + g + (h << 3);
            int ri = (ma << 1) + h;
            int t = (qb << 7) + row_l;
            float inv = 1.f / l_i[ri];
            size_t base = ((size_t)b * T_ + t) * C_ + (hh << 7);
#pragma unroll
            for (int na = 0; na < 4; na++) {
                int d0 = (wq << 5) + (na << 3) + (tig << 1);
                float2 v = make_float2(
                    rnd_tf32(oacc[ma][na][(h << 1) + 0] * inv),
                    rnd_tf32(oacc[ma][na][(h << 1) + 1] * inv));
                *(float2*)(g_ATT + base + d0) = v;
            }
        }
}

// ---------------------------------------------------------------------------
extern "C" void kernel_launch(void* const* d_in, const int* in_sizes, int n_in,
                              void* d_out, int out_size)
{
    const float* x      = (const float*)d_in[0];
    const float* qkv_w  = (const float*)d_in[1];
    const float* qkv_b  = (const float*)d_in[2];
    const float* proj_w = (const float*)d_in[3];
    const float* proj_b = (const float*)d_in[4];
    float* out = (float*)d_out;

    cudaFuncSetAttribute(gemm_mma, cudaFuncAttributeMaxDynamicSharedMemorySize,
                         GEMM_SMEM);
    cudaFuncSetAttribute(attn_mma, cudaFuncAttributeMaxDynamicSharedMemorySize,
                         ATT_SMEM);

    // 0) tf32 pre-round of GEMM inputs
    rnd_prep<<<(B_ * T_ * C_ / 4 + 255) / 256, 256>>>((const float4*)x, 0,
                                                      B_ * T_ * C_ / 4);
    rnd_prep<<<(3 * C_ * C_ / 4 + 255) / 256, 256>>>((const float4*)qkv_w, 1,
                                                     3 * C_ * C_ / 4);
    rnd_prep<<<(C_ * C_ / 4 + 255) / 256, 256>>>((const float4*)proj_w, 2,
                                                 C_ * C_ / 4);

    // 1) QKV projection: [8192,2048] @ [6144,2048]^T + b -> g_Q/g_K/g_V
    gemm_mma<<<dim3(48, 32), 512, GEMM_SMEM>>>(qkv_b, nullptr, 0);

    // 2) causal flash attention (tf32 mma) -> g_ATT [B,T,C]
    attn_mma<<<dim3(T_ / 128, B_ * H_), 256, ATT_SMEM>>>();

    // 3) output projection: g_ATT @ proj_w^T + proj_b -> out
    gemm_mma<<<dim3(16, 32), 512, GEMM_SMEM>>>(proj_b, out, 1);
}

// round 6
// speedup vs baseline: 1.7631x; 1.7631x over previous
#include <cuda_runtime.h>
#include <cuda_fp16.h>
#include <cstdint>

// Problem constants
#define B_ 4
#define T_ 2048
#define C_ 2048
#define H_ 16
#define D_ 128

// Scratch (device globals: allocation-free per harness rules)
__device__ __half g_Qh[(size_t)B_ * H_ * T_ * D_];   // [B,H,T,Dh]
__device__ __half g_Kh[(size_t)B_ * H_ * T_ * D_];
__device__ __half g_Vh[(size_t)B_ * H_ * T_ * D_];
__device__ __half g_ATTh[(size_t)B_ * T_ * C_];      // [B,T,C]
__device__ __half g_xh[(size_t)B_ * T_ * C_];        // half x
__device__ __half g_wqkvh[(size_t)3 * C_ * C_];      // half qkv_w
__device__ __half g_wprojh[(size_t)C_ * C_];         // half proj_w

// ---------------------------------------------------------------------------
// Helpers (sm_80-class PTX only — safe on base sm_103 target)
// ---------------------------------------------------------------------------
__device__ __forceinline__ uint32_t smem_u32(const void* p) {
    uint32_t a;
    asm("{ .reg .u64 t; cvta.to.shared.u64 t, %1; cvt.u32.u64 %0, t; }"
        : "=r"(a) : "l"(p));
    return a;
}
__device__ __forceinline__ void cpa16(uint32_t dst, const void* src) {
    asm volatile("cp.async.cg.shared.global [%0], [%1], 16;"
                 :: "r"(dst), "l"(src));
}
#define CP_COMMIT() asm volatile("cp.async.commit_group;" ::: "memory")
#define CP_WAIT(n)  asm volatile("cp.async.wait_group " #n ";" ::: "memory")

#define LDSM_X4(r0, r1, r2, r3, addr) \
    asm volatile("ldmatrix.sync.aligned.m8n8.x4.shared.b16 {%0,%1,%2,%3}, [%4];" \
        : "=r"(r0), "=r"(r1), "=r"(r2), "=r"(r3) : "r"(addr))
#define LDSM_X4T(r0, r1, r2, r3, addr) \
    asm volatile("ldmatrix.sync.aligned.m8n8.x4.trans.shared.b16 {%0,%1,%2,%3}, [%4];" \
        : "=r"(r0), "=r"(r1), "=r"(r2), "=r"(r3) : "r"(addr))

// D(16x8,f32) += A(16x16,f16) * B(16x8,f16)
__device__ __forceinline__ void mma_h(float c[4], const uint32_t a[4],
                                      const uint32_t b[2]) {
    asm volatile(
        "mma.sync.aligned.m16n8k16.row.col.f32.f16.f16.f32 "
        "{%0,%1,%2,%3}, {%4,%5,%6,%7}, {%8,%9}, {%0,%1,%2,%3};"
        : "+f"(c[0]), "+f"(c[1]), "+f"(c[2]), "+f"(c[3])
        : "r"(a[0]), "r"(a[1]), "r"(a[2]), "r"(a[3]), "r"(b[0]), "r"(b[1]));
}

// ---------------------------------------------------------------------------
// Prep: fp32 -> fp16 convert (one pass per matrix)
// ---------------------------------------------------------------------------
__global__ void prep_h(const float4* __restrict__ src, int which, int n4)
{
    __half* dstb = (which == 0) ? g_xh : (which == 1) ? g_wqkvh : g_wprojh;
    int i = blockIdx.x * blockDim.x + threadIdx.x;
    if (i < n4) {
        float4 v = src[i];
        __half2 h0 = __floats2half2_rn(v.x, v.y);
        __half2 h1 = __floats2half2_rn(v.z, v.w);
        uint2 u;
        u.x = *(uint32_t*)&h0;
        u.y = *(uint32_t*)&h1;
        ((uint2*)dstb)[i] = u;
    }
}

// ===========================================================================
// fp16 GEMM: C[M,N] = A[M,2048] @ W[N,2048]^T + bias[N]   (fp32 accumulate)
// CTA 256x128, 256 threads / 8 warps (4m x 2n) at 64x64 each.
// BK=32 (2 x k16), 3-stage cp.async, ldmatrix fragments, 80B padded rows.
// mode 0: A=g_xh, W=g_wqkvh, half scatter into g_Qh/g_Kh/g_Vh.
// mode 1: A=g_ATTh, W=g_wprojh, fp32 row-major into Out.
// ===========================================================================
#define GRB 80                           // bytes per smem row (32 halfs + pad)
#define GA_B (256 * GRB)                 // A stage bytes = 20480
#define GB_B (128 * GRB)                 // B stage bytes = 10240
#define GEMM_SMEM (3 * (GA_B + GB_B))    // 92160

__global__ void __launch_bounds__(256, 1)
gemm_h(const float* __restrict__ bias, float* __restrict__ Out, int mode)
{
    extern __shared__ char smraw[];
    const __half* A = mode ? g_ATTh : g_xh;
    const __half* W = mode ? g_wprojh : g_wqkvh;
    const int K = C_;

    uint32_t sbase = smem_u32(smraw);
    uint32_t a_sm = sbase;
    uint32_t b_sm = sbase + 3 * GA_B;

    int tid  = threadIdx.x;
    int lane = tid & 31;
    int warp = tid >> 5;                 // 0..7
    int g    = lane >> 2;
    int tig  = lane & 3;
    int wm   = warp >> 1;                // 0..3  (64 rows)
    int wn   = warp & 1;                 // 0..1  (64 cols)
    int bm   = blockIdx.y << 8;
    int bn   = blockIdx.x << 7;

    // staging: 16B chunk id c = tid + 256*s -> row=(tid>>2)+64s, c4=tid&3
    int row0 = tid >> 2;
    int c4   = tid & 3;
    const __half* a_src0 = A + (size_t)(bm + row0) * K + c4 * 8;
    const __half* b_src0 = W + (size_t)(bn + row0) * K + c4 * 8;
    uint32_t stg = (uint32_t)(row0 * GRB + c4 * 16);

    float acc[4][8][4];
#pragma unroll
    for (int i = 0; i < 4; i++)
#pragma unroll
        for (int j = 0; j < 8; j++)
#pragma unroll
            for (int r = 0; r < 4; r++) acc[i][j][r] = 0.f;

    // ldmatrix per-lane address components
    uint32_t a_lane = (uint32_t)((wm * 64 + (lane & 15)) * GRB + ((lane >> 4) << 4));
    uint32_t b_lane = (uint32_t)((wn * 64 + ((lane >> 4) << 3) + (lane & 7)) * GRB +
                                 (((lane >> 3) & 1) << 4));

    // ---- pipeline prologue: stages 0,1 ----
#pragma unroll
    for (int st = 0; st < 2; st++) {
        uint32_t ad = a_sm + st * GA_B + stg;
        uint32_t bd = b_sm + st * GB_B + stg;
#pragma unroll
        for (int s = 0; s < 4; s++)      // A: 256 rows, 64 per step
            cpa16(ad + s * (64 * GRB), a_src0 + (size_t)st * 32 + (size_t)s * 64 * K);
#pragma unroll
        for (int s = 0; s < 2; s++)      // B: 128 rows
            cpa16(bd + s * (64 * GRB), b_src0 + (size_t)st * 32 + (size_t)s * 64 * K);
        CP_COMMIT();
    }

    const int NKT = 64;
    for (int kt = 0; kt < NKT; kt++) {
        if (kt < NKT - 2) { CP_WAIT(1); } else { CP_WAIT(0); }
        __syncthreads();

        if (kt + 2 < NKT) {
            int st = kt + 2;
            int buf = st - (st / 3) * 3;
            uint32_t ad = a_sm + buf * GA_B + stg;
            uint32_t bd = b_sm + buf * GB_B + stg;
#pragma unroll
            for (int s = 0; s < 4; s++)
                cpa16(ad + s * (64 * GRB), a_src0 + (size_t)st * 32 + (size_t)s * 64 * K);
#pragma unroll
            for (int s = 0; s < 2; s++)
                cpa16(bd + s * (64 * GRB), b_src0 + (size_t)st * 32 + (size_t)s * 64 * K);
            CP_COMMIT();
        }

        int buf = kt - (kt / 3) * 3;
        uint32_t Ab = a_sm + buf * GA_B;
        uint32_t Bb = b_sm + buf * GB_B;

#pragma unroll
        for (int ks = 0; ks < 2; ks++) {
            uint32_t af[4][4], bf[8][2];
#pragma unroll
            for (int ma = 0; ma < 4; ma++)
                LDSM_X4(af[ma][0], af[ma][1], af[ma][2], af[ma][3],
                        Ab + a_lane + ma * (16 * GRB) + ks * 32);
#pragma unroll
            for (int np = 0; np < 4; np++)
                LDSM_X4(bf[2 * np][0], bf[2 * np][1], bf[2 * np + 1][0],
                        bf[2 * np + 1][1],
                        Bb + b_lane + np * (16 * GRB) + ks * 32);
#pragma unroll
            for (int ma = 0; ma < 4; ma++)
#pragma unroll
                for (int na = 0; na < 8; na++)
                    mma_h(acc[ma][na], af[ma], bf[na]);
        }
    }

    // ---- epilogue ----
    int sel = blockIdx.x >> 4;           // mode 0: 0:q 1:k 2:v (BN=128 slice)
    int hh  = blockIdx.x & 15;
    __half* qkv_dst = (sel == 0) ? g_Qh : ((sel == 1) ? g_Kh : g_Vh);

#pragma unroll
    for (int ma = 0; ma < 4; ma++) {
        int r0 = bm + (wm << 6) + (ma << 4) + g;
#pragma unroll
        for (int na = 0; na < 8; na++) {
            int cb = (wn << 6) + (na << 3) + (tig << 1);
            int nglob = bn + cb;
            float b0 = __ldg(bias + nglob);
            float b1 = __ldg(bias + nglob + 1);
            if (mode == 0) {
                __half2 v0 = __floats2half2_rn(acc[ma][na][0] + b0,
                                               acc[ma][na][1] + b1);
                __half2 v1 = __floats2half2_rn(acc[ma][na][2] + b0,
                                               acc[ma][na][3] + b1);
                int bb0 = r0 >> 11, t0 = r0 & 2047;
                int r1 = r0 + 8;
                int bb1 = r1 >> 11, t1 = r1 & 2047;
                *(__half2*)(qkv_dst + (((size_t)(bb0 * H_ + hh)) * T_ + t0) * D_ + cb) = v0;
                *(__half2*)(qkv_dst + (((size_t)(bb1 * H_ + hh)) * T_ + t1) * D_ + cb) = v1;
            } else {
                float2 v0 = make_float2(acc[ma][na][0] + b0, acc[ma][na][1] + b1);
                float2 v1 = make_float2(acc[ma][na][2] + b0, acc[ma][na][3] + b1);
                *(float2*)(Out + (size_t)r0 * C_ + nglob)       = v0;
                *(float2*)(Out + (size_t)(r0 + 8) * C_ + nglob) = v1;
            }
        }
    }
}

// ===========================================================================
// Flash attention on fp16 mma (fp32 softmax / accumulators).
// CTA: 128 queries, 8 warps (2q x 4), KB=128 keys per iteration.
// S: warps 64x32 (keys); PV: warps 64x32 (d). P staged half over K buffer.
// Rows padded to 272B (136 halfs) -> conflict-free ldmatrix & cp.async.
// ===========================================================================
#define ARB 272                           // bytes per smem row (128 halfs + pad)
#define TILE_B (128 * ARB)                // 34816
#define ATT_SMEM (3 * TILE_B + 2 * 4 * 128 * 4)   // 108544

__global__ void __launch_bounds__(256, 1)
attn_h()
{
    extern __shared__ char smraw[];
    uint32_t sbase = smem_u32(smraw);
    uint32_t q_sm = sbase;
    uint32_t k_sm = sbase + TILE_B;       // aliased by P after S phase
    uint32_t v_sm = sbase + 2 * TILE_B;
    __half* Ph = (__half*)(smraw + TILE_B);
    float* redm = (float*)(smraw + 3 * TILE_B);    // [4][128]
    float* reds = redm + 4 * 128;                  // [4][128]

    int tid  = threadIdx.x;
    int lane = tid & 31;
    int warp = tid >> 5;
    int g    = lane >> 2;
    int tig  = lane & 3;
    int wm2  = warp >> 2;                 // 0..1 : q rows [wm2*64, +64)
    int wq   = warp & 3;                  // 0..3 : key stripe (S) / d stripe (PV)

    int qb = (int)gridDim.x - 1 - (int)blockIdx.x;   // heavy blocks first
    int bh = blockIdx.y;
    size_t bhoff = (size_t)bh * T_ * D_;

    // staging: chunk id c = tid + 256*s -> row=(tid>>4)+16s, c4=tid&15
    int row0 = tid >> 4;
    int cc4  = tid & 15;
    uint32_t dst_off = (uint32_t)(row0 * ARB + cc4 * 16);
    size_t   src_off = (size_t)row0 * D_ + cc4 * 8;

    // Q tile (once)
    {
        const __half* qsrc = g_Qh + bhoff + (size_t)qb * 128 * D_ + src_off;
#pragma unroll
        for (int s = 0; s < 8; s++)
            cpa16(q_sm + dst_off + s * (16 * ARB), qsrc + (size_t)s * 16 * D_);
        CP_COMMIT();
    }

    // ldmatrix per-lane address components
    uint32_t qa_lane = (uint32_t)((wm2 * 64 + (lane & 15)) * ARB + ((lane >> 4) << 4));
    uint32_t kb_lane = (uint32_t)((wq * 32 + ((lane >> 4) << 3) + (lane & 7)) * ARB +
                                  (((lane >> 3) & 1) << 4));
    uint32_t vb_lane = (uint32_t)(((((lane >> 3) & 1) << 3) + (lane & 7)) * ARB +
                                  wq * 64 + ((lane >> 4) << 4));

    float oacc[4][4][4];
#pragma unroll
    for (int i = 0; i < 4; i++)
#pragma unroll
        for (int j = 0; j < 4; j++)
#pragma unroll
            for (int r = 0; r < 4; r++) oacc[i][j][r] = 0.f;
    float m_i[8], l_i[8];
#pragma unroll
    for (int r = 0; r < 8; r++) { m_i[r] = -1.0e30f; l_i[r] = 0.f; }

    const float scale = 0.088388347648318447f;   // 1/sqrt(128)

    for (int kb = 0; kb <= qb; kb++) {
        __syncthreads();   // prior PV done with P(=K buf) and V
        {
            const __half* ksrc = g_Kh + bhoff + (size_t)kb * 128 * D_ + src_off;
            const __half* vsrc = g_Vh + bhoff + (size_t)kb * 128 * D_ + src_off;
#pragma unroll
            for (int s = 0; s < 8; s++)
                cpa16(k_sm + dst_off + s * (16 * ARB), ksrc + (size_t)s * 16 * D_);
#pragma unroll
            for (int s = 0; s < 8; s++)
                cpa16(v_sm + dst_off + s * (16 * ARB), vsrc + (size_t)s * 16 * D_);
            CP_COMMIT();
        }
        CP_WAIT(0);
        __syncthreads();

        // ---- S = Q K^T : warp 64q x 32keys, 8 k-steps of 16 ----
        float sacc[4][4][4];
#pragma unroll
        for (int i = 0; i < 4; i++)
#pragma unroll
            for (int j = 0; j < 4; j++)
#pragma unroll
                for (int r = 0; r < 4; r++) sacc[i][j][r] = 0.f;

#pragma unroll
        for (int ks = 0; ks < 8; ks++) {
            uint32_t af[4][4], bf[4][2];
#pragma unroll
            for (int ma = 0; ma < 4; ma++)
                LDSM_X4(af[ma][0], af[ma][1], af[ma][2], af[ma][3],
                        q_sm + qa_lane + ma * (16 * ARB) + ks * 32);
#pragma unroll
            for (int np = 0; np < 2; np++)
                LDSM_X4(bf[2 * np][0], bf[2 * np][1], bf[2 * np + 1][0],
                        bf[2 * np + 1][1],
                        k_sm + kb_lane + np * (16 * ARB) + ks * 32);
#pragma unroll
            for (int ma = 0; ma < 4; ma++)
#pragma unroll
                for (int na = 0; na < 4; na++)
                    mma_h(sacc[ma][na], af[ma], bf[na]);
        }

        // ---- softmax bookkeeping (fp32, unchanged structure) ----
        bool diag = (kb == qb);
        float rmax[8];
#pragma unroll
        for (int r = 0; r < 8; r++) rmax[r] = -1.0e30f;
#pragma unroll
        for (int ma = 0; ma < 4; ma++)
#pragma unroll
            for (int h = 0; h < 2; h++) {
                int row_l = (wm2 << 6) + (ma << 4) + g + (h << 3);
                int ri = (ma << 1) + h;
#pragma unroll
                for (int na = 0; na < 4; na++)
#pragma unroll
                    for (int e = 0; e < 2; e++) {
                        int col_l = (wq << 5) + (na << 3) + (tig << 1) + e;
                        float s = sacc[ma][na][(h << 1) + e] * scale;
                        if (diag && col_l > row_l) s = -1.0e30f;
                        sacc[ma][na][(h << 1) + e] = s;
                        rmax[ri] = fmaxf(rmax[ri], s);
                    }
            }
#pragma unroll
        for (int r = 0; r < 8; r++) {
            rmax[r] = fmaxf(rmax[r], __shfl_xor_sync(0xffffffffu, rmax[r], 1));
            rmax[r] = fmaxf(rmax[r], __shfl_xor_sync(0xffffffffu, rmax[r], 2));
        }
        if (tig == 0) {
#pragma unroll
            for (int ma = 0; ma < 4; ma++)
#pragma unroll
                for (int h = 0; h < 2; h++)
                    redm[(wq << 7) + (wm2 << 6) + (ma << 4) + g + (h << 3)] =
                        rmax[(ma << 1) + h];
        }
        __syncthreads();   // also: all warps done with K fragments

        float alpha[8], mnew[8], rsum[8];
#pragma unroll
        for (int ma = 0; ma < 4; ma++)
#pragma unroll
            for (int h = 0; h < 2; h++) {
                int row_l = (wm2 << 6) + (ma << 4) + g + (h << 3);
                int ri = (ma << 1) + h;
                float m4 = fmaxf(fmaxf(redm[row_l], redm[128 + row_l]),
                                 fmaxf(redm[256 + row_l], redm[384 + row_l]));
                mnew[ri] = fmaxf(m_i[ri], m4);
                alpha[ri] = __expf(m_i[ri] - mnew[ri]);
                m_i[ri] = mnew[ri];
                rsum[ri] = 0.f;
            }
        // p = exp(s - m) (fp32), store half into P (over K buffer)
#pragma unroll
        for (int ma = 0; ma < 4; ma++)
#pragma unroll
            for (int h = 0; h < 2; h++) {
                int ri = (ma << 1) + h;
                int row_l = (wm2 << 6) + (ma << 4) + g + (h << 3);
                __half* prow = Ph + (size_t)row_l * 136 + (wq << 5);
#pragma unroll
                for (int na = 0; na < 4; na++) {
                    float p0 = __expf(sacc[ma][na][(h << 1) + 0] - mnew[ri]);
                    float p1 = __expf(sacc[ma][na][(h << 1) + 1] - mnew[ri]);
                    rsum[ri] += p0 + p1;
                    *(__half2*)(prow + (na << 3) + (tig << 1)) =
                        __floats2half2_rn(p0, p1);
                }
            }
#pragma unroll
        for (int r = 0; r < 8; r++) {
            rsum[r] += __shfl_xor_sync(0xffffffffu, rsum[r], 1);
            rsum[r] += __shfl_xor_sync(0xffffffffu, rsum[r], 2);
        }
        if (tig == 0) {
#pragma unroll
            for (int ma = 0; ma < 4; ma++)
#pragma unroll
                for (int h = 0; h < 2; h++)
                    reds[(wq << 7) + (wm2 << 6) + (ma << 4) + g + (h << 3)] =
                        rsum[(ma << 1) + h];
        }
        __syncthreads();   // P fully written, sums ready

#pragma unroll
        for (int ma = 0; ma < 4; ma++)
#pragma unroll
            for (int h = 0; h < 2; h++) {
                int row_l = (wm2 << 6) + (ma << 4) + g + (h << 3);
                int ri = (ma << 1) + h;
                float ls = reds[row_l] + reds[128 + row_l] +
                           reds[256 + row_l] + reds[384 + row_l];
                l_i[ri] = l_i[ri] * alpha[ri] + ls;
            }
#pragma unroll
        for (int ma = 0; ma < 4; ma++)
#pragma unroll
            for (int na = 0; na < 4; na++) {
                oacc[ma][na][0] *= alpha[(ma << 1)];
                oacc[ma][na][1] *= alpha[(ma << 1)];
                oacc[ma][na][2] *= alpha[(ma << 1) + 1];
                oacc[ma][na][3] *= alpha[(ma << 1) + 1];
            }

        // ---- O += P V : warp 64q x 32d, 8 k-steps of 16 keys ----
#pragma unroll
        for (int ks = 0; ks < 8; ks++) {
            uint32_t af[4][4], bf[4][2];
#pragma unroll
            for (int ma = 0; ma < 4; ma++)
                LDSM_X4(af[ma][0], af[ma][1], af[ma][2], af[ma][3],
                        k_sm + qa_lane + ma * (16 * ARB) + ks * 32);
#pragma unroll
            for (int np = 0; np < 2; np++)
                LDSM_X4T(bf[2 * np][0], bf[2 * np][1], bf[2 * np + 1][0],
                         bf[2 * np + 1][1],
                         v_sm + vb_lane + ks * (16 * ARB) + np * 32);
#pragma unroll
            for (int ma = 0; ma < 4; ma++)
#pragma unroll
                for (int na = 0; na < 4; na++)
                    mma_h(oacc[ma][na], af[ma], bf[na]);
        }
    }

    // ---- epilogue: normalize, half-round, write g_ATTh [B,T,C] ----
    int b  = bh >> 4;
    int hh = bh & 15;
#pragma unroll
    for (int ma = 0; ma < 4; ma++)
#pragma unroll
        for (int h = 0; h < 2; h++) {
            int row_l = (wm2 << 6) + (ma << 4) + g + (h << 3);
            int ri = (ma << 1) + h;
            int t = (qb << 7) + row_l;
            float inv = 1.f / l_i[ri];
            size_t base = ((size_t)b * T_ + t) * C_ + (hh << 7);
#pragma unroll
            for (int na = 0; na < 4; na++) {
                int d0 = (wq << 5) + (na << 3) + (tig << 1);
                __half2 v = __floats2half2_rn(oacc[ma][na][(h << 1) + 0] * inv,
                                              oacc[ma][na][(h << 1) + 1] * inv);
                *(__half2*)(g_ATTh + base + d0) = v;
            }
        }
}

// ---------------------------------------------------------------------------
extern "C" void kernel_launch(void* const* d_in, const int* in_sizes, int n_in,
                              void* d_out, int out_size)
{
    const float* x      = (const float*)d_in[0];
    const float* qkv_w  = (const float*)d_in[1];
    const float* qkv_b  = (const float*)d_in[2];
    const float* proj_w = (const float*)d_in[3];
    const float* proj_b = (const float*)d_in[4];
    float* out = (float*)d_out;

    cudaFuncSetAttribute(gemm_h, cudaFuncAttributeMaxDynamicSharedMemorySize,
                         GEMM_SMEM);
    cudaFuncSetAttribute(attn_h, cudaFuncAttributeMaxDynamicSharedMemorySize,
                         ATT_SMEM);

    // 0) fp16 conversion of GEMM inputs
    prep_h<<<(B_ * T_ * C_ / 4 + 255) / 256, 256>>>((const float4*)x, 0,
                                                    B_ * T_ * C_ / 4);
    prep_h<<<(3 * C_ * C_ / 4 + 255) / 256, 256>>>((const float4*)qkv_w, 1,
                                                   3 * C_ * C_ / 4);
    prep_h<<<(C_ * C_ / 4 + 255) / 256, 256>>>((const float4*)proj_w, 2,
                                               C_ * C_ / 4);

    // 1) QKV projection: [8192,2048] @ [6144,2048]^T + b -> g_Qh/g_Kh/g_Vh
    gemm_h<<<dim3(48, 32), 256, GEMM_SMEM>>>(qkv_b, nullptr, 0);

    // 2) causal flash attention (fp16 mma) -> g_ATTh [B,T,C]
    attn_h<<<dim3(T_ / 128, B_ * H_), 256, ATT_SMEM>>>();

    // 3) output projection: g_ATTh @ proj_w^T + proj_b -> out (fp32)
    gemm_h<<<dim3(16, 32), 256, GEMM_SMEM>>>(proj_b, out, 1);
}

// round 7
// speedup vs baseline: 1.9781x; 1.1219x over previous
#include <cuda_runtime.h>
#include <cuda_fp16.h>
#include <cstdint>

// Problem constants
#define B_ 4
#define T_ 2048
#define C_ 2048
#define H_ 16
#define D_ 128

// Scratch (device globals: allocation-free per harness rules)
__device__ __half g_Qh[(size_t)B_ * H_ * T_ * D_];   // [B,H,T,Dh]
__device__ __half g_Kh[(size_t)B_ * H_ * T_ * D_];
__device__ __half g_Vh[(size_t)B_ * H_ * T_ * D_];
__device__ __half g_ATTh[(size_t)B_ * T_ * C_];      // [B,T,C]
__device__ __half g_xh[(size_t)B_ * T_ * C_];        // half x
__device__ __half g_wqkvh[(size_t)3 * C_ * C_];      // half qkv_w
__device__ __half g_wprojh[(size_t)C_ * C_];         // half proj_w

// ---------------------------------------------------------------------------
// Helpers (sm_80-class PTX only — safe on base sm_103 target)
// ---------------------------------------------------------------------------
__device__ __forceinline__ uint32_t smem_u32(const void* p) {
    uint32_t a;
    asm("{ .reg .u64 t; cvta.to.shared.u64 t, %1; cvt.u32.u64 %0, t; }"
        : "=r"(a) : "l"(p));
    return a;
}
__device__ __forceinline__ void cpa16(uint32_t dst, const void* src) {
    asm volatile("cp.async.cg.shared.global [%0], [%1], 16;"
                 :: "r"(dst), "l"(src));
}
#define CP_COMMIT() asm volatile("cp.async.commit_group;" ::: "memory")
#define CP_WAIT(n)  asm volatile("cp.async.wait_group " #n ";" ::: "memory")

#define LDSM_X4(r0, r1, r2, r3, addr) \
    asm volatile("ldmatrix.sync.aligned.m8n8.x4.shared.b16 {%0,%1,%2,%3}, [%4];" \
        : "=r"(r0), "=r"(r1), "=r"(r2), "=r"(r3) : "r"(addr))
#define LDSM_X4T(r0, r1, r2, r3, addr) \
    asm volatile("ldmatrix.sync.aligned.m8n8.x4.trans.shared.b16 {%0,%1,%2,%3}, [%4];" \
        : "=r"(r0), "=r"(r1), "=r"(r2), "=r"(r3) : "r"(addr))

// D(16x8,f32) += A(16x16,f16) * B(16x8,f16)
__device__ __forceinline__ void mma_h(float c[4], const uint32_t a[4],
                                      const uint32_t b[2]) {
    asm volatile(
        "mma.sync.aligned.m16n8k16.row.col.f32.f16.f16.f32 "
        "{%0,%1,%2,%3}, {%4,%5,%6,%7}, {%8,%9}, {%0,%1,%2,%3};"
        : "+f"(c[0]), "+f"(c[1]), "+f"(c[2]), "+f"(c[3])
        : "r"(a[0]), "r"(a[1]), "r"(a[2]), "r"(a[3]), "r"(b[0]), "r"(b[1]));
}

// ---------------------------------------------------------------------------
// Prep: fp32 -> fp16 convert, all three matrices in one launch
// ---------------------------------------------------------------------------
#define NX4  (B_ * T_ * C_ / 4)          // x float4 count
#define NQ4  (3 * C_ * C_ / 4)           // qkv_w
#define NP4  (C_ * C_ / 4)               // proj_w

__global__ void prep_all(const float4* __restrict__ x,
                         const float4* __restrict__ wqkv,
                         const float4* __restrict__ wproj)
{
    int i = blockIdx.x * blockDim.x + threadIdx.x;
    const float4* src;
    __half* dst;
    int j;
    if (i < NX4)            { src = x;     dst = g_xh;     j = i; }
    else if (i < NX4 + NQ4) { src = wqkv;  dst = g_wqkvh;  j = i - NX4; }
    else if (i < NX4 + NQ4 + NP4) { src = wproj; dst = g_wprojh; j = i - NX4 - NQ4; }
    else return;
    float4 v = src[j];
    __half2 h0 = __floats2half2_rn(v.x, v.y);
    __half2 h1 = __floats2half2_rn(v.z, v.w);
    uint2 u;
    u.x = *(uint32_t*)&h0;
    u.y = *(uint32_t*)&h1;
    ((uint2*)dst)[j] = u;
}

// ===========================================================================
// fp16 GEMM: C[M,N] = A[M,2048] @ W[N,2048]^T + bias[N]   (fp32 accumulate)
// CTA 256x128, 8 warps (4m x 2n) at 64x64. BK=64 (4 x k16), 3-stage cp.async,
// ldmatrix fragments with register double-buffering, 144B padded rows.
// mode 0: A=g_xh, W=g_wqkvh, half scatter into g_Qh/g_Kh/g_Vh.
// mode 1: A=g_ATTh, W=g_wprojh, fp32 row-major into Out.
// ===========================================================================
#define GRB 144                          // bytes per smem row (64 halfs + pad)
#define GA_B (256 * GRB)                 // 36864
#define GB_B (128 * GRB)                 // 18432
#define GEMM_SMEM (3 * (GA_B + GB_B))    // 165888

__global__ void __launch_bounds__(256, 1)
gemm_h(const float* __restrict__ bias, float* __restrict__ Out, int mode)
{
    extern __shared__ char smraw[];
    const __half* A = mode ? g_ATTh : g_xh;
    const __half* W = mode ? g_wprojh : g_wqkvh;
    const int K = C_;

    uint32_t sbase = smem_u32(smraw);
    uint32_t a_sm = sbase;
    uint32_t b_sm = sbase + 3 * GA_B;

    int tid  = threadIdx.x;
    int lane = tid & 31;
    int warp = tid >> 5;                 // 0..7
    int g    = lane >> 2;
    int tig  = lane & 3;
    int wm   = warp >> 1;                // 0..3  (64 rows)
    int wn   = warp & 1;                 // 0..1  (64 cols)
    int bm   = blockIdx.y << 8;
    int bn   = blockIdx.x << 7;

    // staging: 16B chunk id c = tid + 256*s -> row=(tid>>3)+32s, c8=tid&7
    int row0 = tid >> 3;                 // 0..31
    int c8   = tid & 7;                  // 0..7 (8 chunks per 128B row)
    const __half* a_src0 = A + (size_t)(bm + row0) * K + c8 * 8;
    const __half* b_src0 = W + (size_t)(bn + row0) * K + c8 * 8;
    uint32_t stg = (uint32_t)(row0 * GRB + c8 * 16);

    float acc[4][8][4];
#pragma unroll
    for (int i = 0; i < 4; i++)
#pragma unroll
        for (int j = 0; j < 8; j++)
#pragma unroll
            for (int r = 0; r < 4; r++) acc[i][j][r] = 0.f;

    // ldmatrix per-lane address components
    uint32_t a_lane = (uint32_t)((wm * 64 + (lane & 15)) * GRB + ((lane >> 4) << 4));
    uint32_t b_lane = (uint32_t)((wn * 64 + ((lane >> 4) << 3) + (lane & 7)) * GRB +
                                 (((lane >> 3) & 1) << 4));

    // ---- pipeline prologue: stages 0,1 ----
#pragma unroll
    for (int st = 0; st < 2; st++) {
        uint32_t ad = a_sm + st * GA_B + stg;
        uint32_t bd = b_sm + st * GB_B + stg;
#pragma unroll
        for (int s = 0; s < 8; s++)      // A: 256 rows, 32 per step
            cpa16(ad + s * (32 * GRB), a_src0 + (size_t)st * 64 + (size_t)s * 32 * K);
#pragma unroll
        for (int s = 0; s < 4; s++)      // B: 128 rows
            cpa16(bd + s * (32 * GRB), b_src0 + (size_t)st * 64 + (size_t)s * 32 * K);
        CP_COMMIT();
    }

    uint32_t af[2][4][4], bf[2][8][2];
#define G_LOAD_FRAGS(d, Ab, Bb, ks) do {                                        \
    _Pragma("unroll")                                                           \
    for (int ma = 0; ma < 4; ma++)                                              \
        LDSM_X4(af[d][ma][0], af[d][ma][1], af[d][ma][2], af[d][ma][3],         \
                (Ab) + a_lane + ma * (16 * GRB) + (ks) * 32);                   \
    _Pragma("unroll")                                                           \
    for (int np = 0; np < 4; np++)                                              \
        LDSM_X4(bf[d][2 * np][0], bf[d][2 * np][1], bf[d][2 * np + 1][0],       \
                bf[d][2 * np + 1][1],                                           \
                (Bb) + b_lane + np * (16 * GRB) + (ks) * 32);                   \
} while (0)

    const int NKT = 32;                  // 2048 / 64
    for (int kt = 0; kt < NKT; kt++) {
        if (kt < NKT - 2) { CP_WAIT(1); } else { CP_WAIT(0); }
        __syncthreads();

        if (kt + 2 < NKT) {
            int st = kt + 2;
            int buf = st - (st / 3) * 3;
            uint32_t ad = a_sm + buf * GA_B + stg;
            uint32_t bd = b_sm + buf * GB_B + stg;
#pragma unroll
            for (int s = 0; s < 8; s++)
                cpa16(ad + s * (32 * GRB), a_src0 + (size_t)st * 64 + (size_t)s * 32 * K);
#pragma unroll
            for (int s = 0; s < 4; s++)
                cpa16(bd + s * (32 * GRB), b_src0 + (size_t)st * 64 + (size_t)s * 32 * K);
            CP_COMMIT();
        }

        int buf = kt - (kt / 3) * 3;
        uint32_t Ab = a_sm + buf * GA_B;
        uint32_t Bb = b_sm + buf * GB_B;

        G_LOAD_FRAGS(0, Ab, Bb, 0);
#pragma unroll
        for (int ks = 0; ks < 4; ks++) {
            int cur = ks & 1;
            if (ks < 3) G_LOAD_FRAGS(cur ^ 1, Ab, Bb, ks + 1);
#pragma unroll
            for (int ma = 0; ma < 4; ma++)
#pragma unroll
                for (int na = 0; na < 8; na++)
                    mma_h(acc[ma][na], af[cur][ma], bf[cur][na]);
        }
    }

    // ---- epilogue ----
    int sel = blockIdx.x >> 4;           // mode 0: 0:q 1:k 2:v (BN=128 slice)
    int hh  = blockIdx.x & 15;
    __half* qkv_dst = (sel == 0) ? g_Qh : ((sel == 1) ? g_Kh : g_Vh);

#pragma unroll
    for (int ma = 0; ma < 4; ma++) {
        int r0 = bm + (wm << 6) + (ma << 4) + g;
#pragma unroll
        for (int na = 0; na < 8; na++) {
            int cb = (wn << 6) + (na << 3) + (tig << 1);
            int nglob = bn + cb;
            float b0 = __ldg(bias + nglob);
            float b1 = __ldg(bias + nglob + 1);
            if (mode == 0) {
                __half2 v0 = __floats2half2_rn(acc[ma][na][0] + b0,
                                               acc[ma][na][1] + b1);
                __half2 v1 = __floats2half2_rn(acc[ma][na][2] + b0,
                                               acc[ma][na][3] + b1);
                int bb0 = r0 >> 11, t0 = r0 & 2047;
                int r1 = r0 + 8;
                int bb1 = r1 >> 11, t1 = r1 & 2047;
                *(__half2*)(qkv_dst + (((size_t)(bb0 * H_ + hh)) * T_ + t0) * D_ + cb) = v0;
                *(__half2*)(qkv_dst + (((size_t)(bb1 * H_ + hh)) * T_ + t1) * D_ + cb) = v1;
            } else {
                float2 v0 = make_float2(acc[ma][na][0] + b0, acc[ma][na][1] + b1);
                float2 v1 = make_float2(acc[ma][na][2] + b0, acc[ma][na][3] + b1);
                *(float2*)(Out + (size_t)r0 * C_ + nglob)       = v0;
                *(float2*)(Out + (size_t)(r0 + 8) * C_ + nglob) = v1;
            }
        }
    }
}

// ===========================================================================
// Flash attention on fp16 mma (fp32 softmax / accumulators) — unchanged from
// Round-6 passing version.
// ===========================================================================
#define ARB 272                           // bytes per smem row (128 halfs + pad)
#define TILE_B (128 * ARB)                // 34816
#define ATT_SMEM (3 * TILE_B + 2 * 4 * 128 * 4)   // 108544

__global__ void __launch_bounds__(256, 1)
attn_h()
{
    extern __shared__ char smraw[];
    uint32_t sbase = smem_u32(smraw);
    uint32_t q_sm = sbase;
    uint32_t k_sm = sbase + TILE_B;       // aliased by P after S phase
    uint32_t v_sm = sbase + 2 * TILE_B;
    __half* Ph = (__half*)(smraw + TILE_B);
    float* redm = (float*)(smraw + 3 * TILE_B);    // [4][128]
    float* reds = redm + 4 * 128;                  // [4][128]

    int tid  = threadIdx.x;
    int lane = tid & 31;
    int warp = tid >> 5;
    int g    = lane >> 2;
    int tig  = lane & 3;
    int wm2  = warp >> 2;                 // 0..1 : q rows [wm2*64, +64)
    int wq   = warp & 3;                  // 0..3 : key stripe (S) / d stripe (PV)

    int qb = (int)gridDim.x - 1 - (int)blockIdx.x;   // heavy blocks first
    int bh = blockIdx.y;
    size_t bhoff = (size_t)bh * T_ * D_;

    // staging: chunk id c = tid + 256*s -> row=(tid>>4)+16s, c4=tid&15
    int row0 = tid >> 4;
    int cc4  = tid & 15;
    uint32_t dst_off = (uint32_t)(row0 * ARB + cc4 * 16);
    size_t   src_off = (size_t)row0 * D_ + cc4 * 8;

    // Q tile (once)
    {
        const __half* qsrc = g_Qh + bhoff + (size_t)qb * 128 * D_ + src_off;
#pragma unroll
        for (int s = 0; s < 8; s++)
            cpa16(q_sm + dst_off + s * (16 * ARB), qsrc + (size_t)s * 16 * D_);
        CP_COMMIT();
    }

    // ldmatrix per-lane address components
    uint32_t qa_lane = (uint32_t)((wm2 * 64 + (lane & 15)) * ARB + ((lane >> 4) << 4));
    uint32_t kb_lane = (uint32_t)((wq * 32 + ((lane >> 4) << 3) + (lane & 7)) * ARB +
                                  (((lane >> 3) & 1) << 4));
    uint32_t vb_lane = (uint32_t)(((((lane >> 3) & 1) << 3) + (lane & 7)) * ARB +
                                  wq * 64 + ((lane >> 4) << 4));

    float oacc[4][4][4];
#pragma unroll
    for (int i = 0; i < 4; i++)
#pragma unroll
        for (int j = 0; j < 4; j++)
#pragma unroll
            for (int r = 0; r < 4; r++) oacc[i][j][r] = 0.f;
    float m_i[8], l_i[8];
#pragma unroll
    for (int r = 0; r < 8; r++) { m_i[r] = -1.0e30f; l_i[r] = 0.f; }

    const float scale = 0.088388347648318447f;   // 1/sqrt(128)

    for (int kb = 0; kb <= qb; kb++) {
        __syncthreads();   // prior PV done with P(=K buf) and V
        {
            const __half* ksrc = g_Kh + bhoff + (size_t)kb * 128 * D_ + src_off;
            const __half* vsrc = g_Vh + bhoff + (size_t)kb * 128 * D_ + src_off;
#pragma unroll
            for (int s = 0; s < 8; s++)
                cpa16(k_sm + dst_off + s * (16 * ARB), ksrc + (size_t)s * 16 * D_);
#pragma unroll
            for (int s = 0; s < 8; s++)
                cpa16(v_sm + dst_off + s * (16 * ARB), vsrc + (size_t)s * 16 * D_);
            CP_COMMIT();
        }
        CP_WAIT(0);
        __syncthreads();

        // ---- S = Q K^T : warp 64q x 32keys, 8 k-steps of 16 ----
        float sacc[4][4][4];
#pragma unroll
        for (int i = 0; i < 4; i++)
#pragma unroll
            for (int j = 0; j < 4; j++)
#pragma unroll
                for (int r = 0; r < 4; r++) sacc[i][j][r] = 0.f;

#pragma unroll
        for (int ks = 0; ks < 8; ks++) {
            uint32_t af[4][4], bf[4][2];
#pragma unroll
            for (int ma = 0; ma < 4; ma++)
                LDSM_X4(af[ma][0], af[ma][1], af[ma][2], af[ma][3],
                        q_sm + qa_lane + ma * (16 * ARB) + ks * 32);
#pragma unroll
            for (int np = 0; np < 2; np++)
                LDSM_X4(bf[2 * np][0], bf[2 * np][1], bf[2 * np + 1][0],
                        bf[2 * np + 1][1],
                        k_sm + kb_lane + np * (16 * ARB) + ks * 32);
#pragma unroll
            for (int ma = 0; ma < 4; ma++)
#pragma unroll
                for (int na = 0; na < 4; na++)
                    mma_h(sacc[ma][na], af[ma], bf[na]);
        }

        // ---- softmax bookkeeping (fp32) ----
        bool diag = (kb == qb);
        float rmax[8];
#pragma unroll
        for (int r = 0; r < 8; r++) rmax[r] = -1.0e30f;
#pragma unroll
        for (int ma = 0; ma < 4; ma++)
#pragma unroll
            for (int h = 0; h < 2; h++) {
                int row_l = (wm2 << 6) + (ma << 4) + g + (h << 3);
                int ri = (ma << 1) + h;
#pragma unroll
                for (int na = 0; na < 4; na++)
#pragma unroll
                    for (int e = 0; e < 2; e++) {
                        int col_l = (wq << 5) + (na << 3) + (tig << 1) + e;
                        float s = sacc[ma][na][(h << 1) + e] * scale;
                        if (diag && col_l > row_l) s = -1.0e30f;
                        sacc[ma][na][(h << 1) + e] = s;
                        rmax[ri] = fmaxf(rmax[ri], s);
                    }
            }
#pragma unroll
        for (int r = 0; r < 8; r++) {
            rmax[r] = fmaxf(rmax[r], __shfl_xor_sync(0xffffffffu, rmax[r], 1));
            rmax[r] = fmaxf(rmax[r], __shfl_xor_sync(0xffffffffu, rmax[r], 2));
        }
        if (tig == 0) {
#pragma unroll
            for (int ma = 0; ma < 4; ma++)
#pragma unroll
                for (int h = 0; h < 2; h++)
                    redm[(wq << 7) + (wm2 << 6) + (ma << 4) + g + (h << 3)] =
                        rmax[(ma << 1) + h];
        }
        __syncthreads();   // also: all warps done with K fragments

        float alpha[8], mnew[8], rsum[8];
#pragma unroll
        for (int ma = 0; ma < 4; ma++)
#pragma unroll
            for (int h = 0; h < 2; h++) {
                int row_l = (wm2 << 6) + (ma << 4) + g + (h << 3);
                int ri = (ma << 1) + h;
                float m4 = fmaxf(fmaxf(redm[row_l], redm[128 + row_l]),
                                 fmaxf(redm[256 + row_l], redm[384 + row_l]));
                mnew[ri] = fmaxf(m_i[ri], m4);
                alpha[ri] = __expf(m_i[ri] - mnew[ri]);
                m_i[ri] = mnew[ri];
                rsum[ri] = 0.f;
            }
        // p = exp(s - m) (fp32), store half into P (over K buffer)
#pragma unroll
        for (int ma = 0; ma < 4; ma++)
#pragma unroll
            for (int h = 0; h < 2; h++) {
                int ri = (ma << 1) + h;
                int row_l = (wm2 << 6) + (ma << 4) + g + (h << 3);
                __half* prow = Ph + (size_t)row_l * 136 + (wq << 5);
#pragma unroll
                for (int na = 0; na < 4; na++) {
                    float p0 = __expf(sacc[ma][na][(h << 1) + 0] - mnew[ri]);
                    float p1 = __expf(sacc[ma][na][(h << 1) + 1] - mnew[ri]);
                    rsum[ri] += p0 + p1;
                    *(__half2*)(prow + (na << 3) + (tig << 1)) =
                        __floats2half2_rn(p0, p1);
                }
            }
#pragma unroll
        for (int r = 0; r < 8; r++) {
            rsum[r] += __shfl_xor_sync(0xffffffffu, rsum[r], 1);
            rsum[r] += __shfl_xor_sync(0xffffffffu, rsum[r], 2);
        }
        if (tig == 0) {
#pragma unroll
            for (int ma = 0; ma < 4; ma++)
#pragma unroll
                for (int h = 0; h < 2; h++)
                    reds[(wq << 7) + (wm2 << 6) + (ma << 4) + g + (h << 3)] =
                        rsum[(ma << 1) + h];
        }
        __syncthreads();   // P fully written, sums ready

#pragma unroll
        for (int ma = 0; ma < 4; ma++)
#pragma unroll
            for (int h = 0; h < 2; h++) {
                int row_l = (wm2 << 6) + (ma << 4) + g + (h << 3);
                int ri = (ma << 1) + h;
                float ls = reds[row_l] + reds[128 + row_l] +
                           reds[256 + row_l] + reds[384 + row_l];
                l_i[ri] = l_i[ri] * alpha[ri] + ls;
            }
#pragma unroll
        for (int ma = 0; ma < 4; ma++)
#pragma unroll
            for (int na = 0; na < 4; na++) {
                oacc[ma][na][0] *= alpha[(ma << 1)];
                oacc[ma][na][1] *= alpha[(ma << 1)];
                oacc[ma][na][2] *= alpha[(ma << 1) + 1];
                oacc[ma][na][3] *= alpha[(ma << 1) + 1];
            }

        // ---- O += P V : warp 64q x 32d, 8 k-steps of 16 keys ----
#pragma unroll
        for (int ks = 0; ks < 8; ks++) {
            uint32_t af[4][4], bf[4][2];
#pragma unroll
            for (int ma = 0; ma < 4; ma++)
                LDSM_X4(af[ma][0], af[ma][1], af[ma][2], af[ma][3],
                        k_sm + qa_lane + ma * (16 * ARB) + ks * 32);
#pragma unroll
            for (int np = 0; np < 2; np++)
                LDSM_X4T(bf[2 * np][0], bf[2 * np][1], bf[2 * np + 1][0],
                         bf[2 * np + 1][1],
                         v_sm + vb_lane + ks * (16 * ARB) + np * 32);
#pragma unroll
            for (int ma = 0; ma < 4; ma++)
#pragma unroll
                for (int na = 0; na < 4; na++)
                    mma_h(oacc[ma][na], af[ma], bf[na]);
        }
    }

    // ---- epilogue: normalize, half-round, write g_ATTh [B,T,C] ----
    int b  = bh >> 4;
    int hh = bh & 15;
#pragma unroll
    for (int ma = 0; ma < 4; ma++)
#pragma unroll
        for (int h = 0; h < 2; h++) {
            int row_l = (wm2 << 6) + (ma << 4) + g + (h << 3);
            int ri = (ma << 1) + h;
            int t = (qb << 7) + row_l;
            float inv = 1.f / l_i[ri];
            size_t base = ((size_t)b * T_ + t) * C_ + (hh << 7);
#pragma unroll
            for (int na = 0; na < 4; na++) {
                int d0 = (wq << 5) + (na << 3) + (tig << 1);
                __half2 v = __floats2half2_rn(oacc[ma][na][(h << 1) + 0] * inv,
                                              oacc[ma][na][(h << 1) + 1] * inv);
                *(__half2*)(g_ATTh + base + d0) = v;
            }
        }
}

// ---------------------------------------------------------------------------
extern "C" void kernel_launch(void* const* d_in, const int* in_sizes, int n_in,
                              void* d_out, int out_size)
{
    const float* x      = (const float*)d_in[0];
    const float* qkv_w  = (const float*)d_in[1];
    const float* qkv_b  = (const float*)d_in[2];
    const float* proj_w = (const float*)d_in[3];
    const float* proj_b = (const float*)d_in[4];
    float* out = (float*)d_out;

    cudaFuncSetAttribute(gemm_h, cudaFuncAttributeMaxDynamicSharedMemorySize,
                         GEMM_SMEM);
    cudaFuncSetAttribute(attn_h, cudaFuncAttributeMaxDynamicSharedMemorySize,
                         ATT_SMEM);

    // 0) fp16 conversion of all GEMM inputs (single launch)
    prep_all<<<(NX4 + NQ4 + NP4 + 255) / 256, 256>>>(
        (const float4*)x, (const float4*)qkv_w, (const float4*)proj_w);

    // 1) QKV projection: [8192,2048] @ [6144,2048]^T + b -> g_Qh/g_Kh/g_Vh
    gemm_h<<<dim3(48, 32), 256, GEMM_SMEM>>>(qkv_b, nullptr, 0);

    // 2) causal flash attention (fp16 mma) -> g_ATTh [B,T,C]
    attn_h<<<dim3(T_ / 128, B_ * H_), 256, ATT_SMEM>>>();

    // 3) output projection: g_ATTh @ proj_w^T + proj_b -> out (fp32)
    gemm_h<<<dim3(16, 32), 256, GEMM_SMEM>>>(proj_b, out, 1);
}

// round 8
// speedup vs baseline: 1.9911x; 1.0066x over previous
#include <cuda_runtime.h>
#include <cuda_fp16.h>
#include <cstdint>

// Problem constants
#define B_ 4
#define T_ 2048
#define C_ 2048
#define H_ 16
#define D_ 128

// Scratch (device globals: allocation-free per harness rules)
__device__ __half g_Qh[(size_t)B_ * H_ * T_ * D_];   // [B,H,T,Dh]
__device__ __half g_Kh[(size_t)B_ * H_ * T_ * D_];
__device__ __half g_Vh[(size_t)B_ * H_ * T_ * D_];
__device__ __half g_ATTh[(size_t)B_ * T_ * C_];      // [B,T,C]
__device__ __half g_xh[(size_t)B_ * T_ * C_];        // half x
__device__ __half g_wqkvh[(size_t)3 * C_ * C_];      // half qkv_w
__device__ __half g_wprojh[(size_t)C_ * C_];         // half proj_w

// ---------------------------------------------------------------------------
// Helpers (sm_80-class PTX only — safe on base sm_103 target)
// ---------------------------------------------------------------------------
__device__ __forceinline__ uint32_t smem_u32(const void* p) {
    uint32_t a;
    asm("{ .reg .u64 t; cvta.to.shared.u64 t, %1; cvt.u32.u64 %0, t; }"
        : "=r"(a) : "l"(p));
    return a;
}
__device__ __forceinline__ void cpa16(uint32_t dst, const void* src) {
    asm volatile("cp.async.cg.shared.global [%0], [%1], 16;"
                 :: "r"(dst), "l"(src));
}
#define CP_COMMIT() asm volatile("cp.async.commit_group;" ::: "memory")
#define CP_WAIT(n)  asm volatile("cp.async.wait_group " #n ";" ::: "memory")

#define LDSM_X4(r0, r1, r2, r3, addr) \
    asm volatile("ldmatrix.sync.aligned.m8n8.x4.shared.b16 {%0,%1,%2,%3}, [%4];" \
        : "=r"(r0), "=r"(r1), "=r"(r2), "=r"(r3) : "r"(addr))
#define LDSM_X4T(r0, r1, r2, r3, addr) \
    asm volatile("ldmatrix.sync.aligned.m8n8.x4.trans.shared.b16 {%0,%1,%2,%3}, [%4];" \
        : "=r"(r0), "=r"(r1), "=r"(r2), "=r"(r3) : "r"(addr))

// D(16x8,f32) += A(16x16,f16) * B(16x8,f16)
__device__ __forceinline__ void mma_h(float c[4], const uint32_t a[4],
                                      const uint32_t b[2]) {
    asm volatile(
        "mma.sync.aligned.m16n8k16.row.col.f32.f16.f16.f32 "
        "{%0,%1,%2,%3}, {%4,%5,%6,%7}, {%8,%9}, {%0,%1,%2,%3};"
        : "+f"(c[0]), "+f"(c[1]), "+f"(c[2]), "+f"(c[3])
        : "r"(a[0]), "r"(a[1]), "r"(a[2]), "r"(a[3]), "r"(b[0]), "r"(b[1]));
}

// ---------------------------------------------------------------------------
// Prep: fp32 -> fp16 convert, all three matrices in one launch
// ---------------------------------------------------------------------------
#define NX4  (B_ * T_ * C_ / 4)
#define NQ4  (3 * C_ * C_ / 4)
#define NP4  (C_ * C_ / 4)

__global__ void prep_all(const float4* __restrict__ x,
                         const float4* __restrict__ wqkv,
                         const float4* __restrict__ wproj)
{
    int i = blockIdx.x * blockDim.x + threadIdx.x;
    const float4* src;
    __half* dst;
    int j;
    if (i < NX4)            { src = x;     dst = g_xh;     j = i; }
    else if (i < NX4 + NQ4) { src = wqkv;  dst = g_wqkvh;  j = i - NX4; }
    else if (i < NX4 + NQ4 + NP4) { src = wproj; dst = g_wprojh; j = i - NX4 - NQ4; }
    else return;
    float4 v = src[j];
    __half2 h0 = __floats2half2_rn(v.x, v.y);
    __half2 h1 = __floats2half2_rn(v.z, v.w);
    uint2 u;
    u.x = *(uint32_t*)&h0;
    u.y = *(uint32_t*)&h1;
    ((uint2*)dst)[j] = u;
}

// ===========================================================================
// fp16 GEMM: C[M,N] = A[M,2048] @ W[N,2048]^T + bias[N]   (fp32 accumulate)
// CTA 128x128, 8 warps (2m x 4n) at 64x32. BK=128 (8 x k16), 3-stage
// cp.async, ldmatrix fragments w/ register double-buffering, 272B rows.
// Grids: QKV (48,64)=3072 CTAs, proj (16,64)=1024 CTAs -> ~1% wave tails.
// mode 0: A=g_xh, W=g_wqkvh, half scatter into g_Qh/g_Kh/g_Vh.
// mode 1: A=g_ATTh, W=g_wprojh, fp32 row-major into Out.
// ===========================================================================
#define GRB 272                          // bytes per smem row (128 halfs + pad)
#define STG_B (256 * GRB)                // per stage: A 128 rows + B 128 rows
#define GEMM_SMEM (3 * STG_B)            // 208896

__global__ void __launch_bounds__(256, 1)
gemm_h(const float* __restrict__ bias, float* __restrict__ Out, int mode)
{
    extern __shared__ char smraw[];
    const __half* A = mode ? g_ATTh : g_xh;
    const __half* W = mode ? g_wprojh : g_wqkvh;
    const int K = C_;

    uint32_t sbase = smem_u32(smraw);

    int tid  = threadIdx.x;
    int lane = tid & 31;
    int warp = tid >> 5;                 // 0..7
    int g    = lane >> 2;
    int tig  = lane & 3;
    int wm   = warp >> 2;                // 0..1  (64 rows)
    int wn   = warp & 3;                 // 0..3  (32 cols)
    int bm   = blockIdx.y << 7;
    int bn   = blockIdx.x << 7;

    // staging: per pass s, rows 16s + (tid>>4), 16B chunk col = tid&15
    int row0 = tid >> 4;                 // 0..15
    int c16  = tid & 15;                 // 0..15
    const __half* a_src0 = A + (size_t)(bm + row0) * K + c16 * 8;
    const __half* b_src0 = W + (size_t)(bn + row0) * K + c16 * 8;
    uint32_t stg_a = (uint32_t)(row0 * GRB + c16 * 16);
    uint32_t stg_b = stg_a + 128 * GRB;

    float acc[4][4][4];
#pragma unroll
    for (int i = 0; i < 4; i++)
#pragma unroll
        for (int j = 0; j < 4; j++)
#pragma unroll
            for (int r = 0; r < 4; r++) acc[i][j][r] = 0.f;

    // ldmatrix per-lane address components (relative to stage base)
    uint32_t a_lane = (uint32_t)((wm * 64 + (lane & 15)) * GRB + ((lane >> 4) << 4));
    uint32_t b_lane = (uint32_t)(128 * GRB +
                      (wn * 32 + ((lane >> 4) << 3) + (lane & 7)) * GRB +
                      (((lane >> 3) & 1) << 4));

    // ---- pipeline prologue: stages 0,1 ----
#pragma unroll
    for (int st = 0; st < 2; st++) {
        uint32_t ad = sbase + st * STG_B + stg_a;
        uint32_t bd = sbase + st * STG_B + stg_b;
#pragma unroll
        for (int s = 0; s < 8; s++)
            cpa16(ad + s * (16 * GRB), a_src0 + (size_t)st * 128 + (size_t)s * 16 * K);
#pragma unroll
        for (int s = 0; s < 8; s++)
            cpa16(bd + s * (16 * GRB), b_src0 + (size_t)st * 128 + (size_t)s * 16 * K);
        CP_COMMIT();
    }

    uint32_t af[2][4][4], bf[2][4][2];
#define G_LOAD_FRAGS(d, Sb, ks) do {                                            \
    _Pragma("unroll")                                                           \
    for (int ma = 0; ma < 4; ma++)                                              \
        LDSM_X4(af[d][ma][0], af[d][ma][1], af[d][ma][2], af[d][ma][3],         \
                (Sb) + a_lane + ma * (16 * GRB) + (ks) * 32);                   \
    _Pragma("unroll")                                                           \
    for (int np = 0; np < 2; np++)                                              \
        LDSM_X4(bf[d][2 * np][0], bf[d][2 * np][1], bf[d][2 * np + 1][0],       \
                bf[d][2 * np + 1][1],                                           \
                (Sb) + b_lane + np * (16 * GRB) + (ks) * 32);                   \
} while (0)

    const int NKT = 16;                  // 2048 / 128
    for (int kt = 0; kt < NKT; kt++) {
        if (kt < NKT - 2) { CP_WAIT(1); } else { CP_WAIT(0); }
        __syncthreads();

        if (kt + 2 < NKT) {
            int st = kt + 2;
            int buf = st - (st / 3) * 3;
            uint32_t ad = sbase + buf * STG_B + stg_a;
            uint32_t bd = sbase + buf * STG_B + stg_b;
#pragma unroll
            for (int s = 0; s < 8; s++)
                cpa16(ad + s * (16 * GRB), a_src0 + (size_t)st * 128 + (size_t)s * 16 * K);
#pragma unroll
            for (int s = 0; s < 8; s++)
                cpa16(bd + s * (16 * GRB), b_src0 + (size_t)st * 128 + (size_t)s * 16 * K);
            CP_COMMIT();
        }

        int buf = kt - (kt / 3) * 3;
        uint32_t Sb = sbase + buf * STG_B;

        G_LOAD_FRAGS(0, Sb, 0);
#pragma unroll
        for (int ks = 0; ks < 8; ks++) {
            int cur = ks & 1;
            if (ks < 7) G_LOAD_FRAGS(cur ^ 1, Sb, ks + 1);
#pragma unroll
            for (int ma = 0; ma < 4; ma++)
#pragma unroll
                for (int na = 0; na < 4; na++)
                    mma_h(acc[ma][na], af[cur][ma], bf[cur][na]);
        }
    }

    // ---- epilogue ----
    int sel = blockIdx.x >> 4;           // mode 0: 0:q 1:k 2:v (BN=128 slice)
    int hh  = blockIdx.x & 15;
    __half* qkv_dst = (sel == 0) ? g_Qh : ((sel == 1) ? g_Kh : g_Vh);

#pragma unroll
    for (int ma = 0; ma < 4; ma++) {
        int r0 = bm + (wm << 6) + (ma << 4) + g;
#pragma unroll
        for (int na = 0; na < 4; na++) {
            int cb = (wn << 5) + (na << 3) + (tig << 1);
            int nglob = bn + cb;
            float b0 = __ldg(bias + nglob);
            float b1 = __ldg(bias + nglob + 1);
            if (mode == 0) {
                __half2 v0 = __floats2half2_rn(acc[ma][na][0] + b0,
                                               acc[ma][na][1] + b1);
                __half2 v1 = __floats2half2_rn(acc[ma][na][2] + b0,
                                               acc[ma][na][3] + b1);
                int bb0 = r0 >> 11, t0 = r0 & 2047;
                int r1 = r0 + 8;
                int bb1 = r1 >> 11, t1 = r1 & 2047;
                *(__half2*)(qkv_dst + (((size_t)(bb0 * H_ + hh)) * T_ + t0) * D_ + cb) = v0;
                *(__half2*)(qkv_dst + (((size_t)(bb1 * H_ + hh)) * T_ + t1) * D_ + cb) = v1;
            } else {
                float2 v0 = make_float2(acc[ma][na][0] + b0, acc[ma][na][1] + b1);
                float2 v1 = make_float2(acc[ma][na][2] + b0, acc[ma][na][3] + b1);
                *(float2*)(Out + (size_t)r0 * C_ + nglob)       = v0;
                *(float2*)(Out + (size_t)(r0 + 8) * C_ + nglob) = v1;
            }
        }
    }
}

// ===========================================================================
// Flash attention on fp16 mma (fp32 softmax / accumulators).
// Round-7 structure + double-buffered K/V: prefetch kb+1 during kb compute.
// smem: [Q][K0][V0][K1][V1][red] = 5 tiles + 4KB = 178176 bytes.
// P for iteration kb aliases K[kb&1] (freed before buf^1 is re-staged).
// ===========================================================================
#define ARB 272                           // bytes per smem row (128 halfs + pad)
#define TILE_B (128 * ARB)                // 34816
#define ATT_SMEM (5 * TILE_B + 2 * 4 * 128 * 4)   // 178176

__global__ void __launch_bounds__(256, 1)
attn_h()
{
    extern __shared__ char smraw[];
    uint32_t sbase = smem_u32(smraw);
    uint32_t q_sm = sbase;
    float* redm = (float*)(smraw + 5 * TILE_B);    // [4][128]
    float* reds = redm + 4 * 128;                  // [4][128]

    int tid  = threadIdx.x;
    int lane = tid & 31;
    int warp = tid >> 5;
    int g    = lane >> 2;
    int tig  = lane & 3;
    int wm2  = warp >> 2;                 // 0..1 : q rows [wm2*64, +64)
    int wq   = warp & 3;                  // 0..3 : key stripe (S) / d stripe (PV)

    int qb = (int)gridDim.x - 1 - (int)blockIdx.x;   // heavy blocks first
    int bh = blockIdx.y;
    size_t bhoff = (size_t)bh * T_ * D_;

    // staging: chunk id c = tid + 256*s -> row=(tid>>4)+16s, c4=tid&15
    int row0 = tid >> 4;
    int cc4  = tid & 15;
    uint32_t dst_off = (uint32_t)(row0 * ARB + cc4 * 16);
    size_t   src_off = (size_t)row0 * D_ + cc4 * 8;

    // Q tile (once)
    {
        const __half* qsrc = g_Qh + bhoff + (size_t)qb * 128 * D_ + src_off;
#pragma unroll
        for (int s = 0; s < 8; s++)
            cpa16(q_sm + dst_off + s * (16 * ARB), qsrc + (size_t)s * 16 * D_);
        CP_COMMIT();
    }
    // K/V kb=0 into buffer 0
    {
        const __half* ksrc = g_Kh + bhoff + src_off;
        const __half* vsrc = g_Vh + bhoff + src_off;
        uint32_t k0 = sbase + TILE_B;
        uint32_t v0 = sbase + 2 * TILE_B;
#pragma unroll
        for (int s = 0; s < 8; s++)
            cpa16(k0 + dst_off + s * (16 * ARB), ksrc + (size_t)s * 16 * D_);
#pragma unroll
        for (int s = 0; s < 8; s++)
            cpa16(v0 + dst_off + s * (16 * ARB), vsrc + (size_t)s * 16 * D_);
        CP_COMMIT();
    }

    // ldmatrix per-lane address components (relative to tile bases)
    uint32_t qa_lane = (uint32_t)((wm2 * 64 + (lane & 15)) * ARB + ((lane >> 4) << 4));
    uint32_t kb_rel  = (uint32_t)((wq * 32 + ((lane >> 4) << 3) + (lane & 7)) * ARB +
                                  (((lane >> 3) & 1) << 4));
    uint32_t vb_rel  = (uint32_t)(((((lane >> 3) & 1) << 3) + (lane & 7)) * ARB +
                                  wq * 64 + ((lane >> 4) << 4));

    float oacc[4][4][4];
#pragma unroll
    for (int i = 0; i < 4; i++)
#pragma unroll
        for (int j = 0; j < 4; j++)
#pragma unroll
            for (int r = 0; r < 4; r++) oacc[i][j][r] = 0.f;
    float m_i[8], l_i[8];
#pragma unroll
    for (int r = 0; r < 8; r++) { m_i[r] = -1.0e30f; l_i[r] = 0.f; }

    const float scale = 0.088388347648318447f;   // 1/sqrt(128)

    for (int kb = 0; kb <= qb; kb++) {
        int buf = kb & 1;
        uint32_t k_sm = sbase + TILE_B + (uint32_t)buf * (2 * TILE_B);
        uint32_t v_sm = k_sm + TILE_B;

        __syncthreads();   // prior PV done with P(=K[buf^1]) and V[buf^1]

        if (kb < qb) {     // prefetch kb+1 into the other buffer
            uint32_t kn = sbase + TILE_B + (uint32_t)(buf ^ 1) * (2 * TILE_B);
            uint32_t vn = kn + TILE_B;
            const __half* ksrc = g_Kh + bhoff + (size_t)(kb + 1) * 128 * D_ + src_off;
            const __half* vsrc = g_Vh + bhoff + (size_t)(kb + 1) * 128 * D_ + src_off;
#pragma unroll
            for (int s = 0; s < 8; s++)
                cpa16(kn + dst_off + s * (16 * ARB), ksrc + (size_t)s * 16 * D_);
#pragma unroll
            for (int s = 0; s < 8; s++)
                cpa16(vn + dst_off + s * (16 * ARB), vsrc + (size_t)s * 16 * D_);
            CP_COMMIT();
            CP_WAIT(1);    // kb's data complete; kb+1 still in flight
        } else {
            CP_WAIT(0);
        }
        __syncthreads();

        // ---- S = Q K^T : warp 64q x 32keys, 8 k-steps of 16 ----
        float sacc[4][4][4];
#pragma unroll
        for (int i = 0; i < 4; i++)
#pragma unroll
            for (int j = 0; j < 4; j++)
#pragma unroll
                for (int r = 0; r < 4; r++) sacc[i][j][r] = 0.f;

#pragma unroll
        for (int ks = 0; ks < 8; ks++) {
            uint32_t af[4][4], bf[4][2];
#pragma unroll
            for (int ma = 0; ma < 4; ma++)
                LDSM_X4(af[ma][0], af[ma][1], af[ma][2], af[ma][3],
                        q_sm + qa_lane + ma * (16 * ARB) + ks * 32);
#pragma unroll
            for (int np = 0; np < 2; np++)
                LDSM_X4(bf[2 * np][0], bf[2 * np][1], bf[2 * np + 1][0],
                        bf[2 * np + 1][1],
                        k_sm + kb_rel + np * (16 * ARB) + ks * 32);
#pragma unroll
            for (int ma = 0; ma < 4; ma++)
#pragma unroll
                for (int na = 0; na < 4; na++)
                    mma_h(sacc[ma][na], af[ma], bf[na]);
        }

        // ---- softmax bookkeeping (fp32) ----
        bool diag = (kb == qb);
        float rmax[8];
#pragma unroll
        for (int r = 0; r < 8; r++) rmax[r] = -1.0e30f;
#pragma unroll
        for (int ma = 0; ma < 4; ma++)
#pragma unroll
            for (int h = 0; h < 2; h++) {
                int row_l = (wm2 << 6) + (ma << 4) + g + (h << 3);
                int ri = (ma << 1) + h;
#pragma unroll
                for (int na = 0; na < 4; na++)
#pragma unroll
                    for (int e = 0; e < 2; e++) {
                        int col_l = (wq << 5) + (na << 3) + (tig << 1) + e;
                        float s = sacc[ma][na][(h << 1) + e] * scale;
                        if (diag && col_l > row_l) s = -1.0e30f;
                        sacc[ma][na][(h << 1) + e] = s;
                        rmax[ri] = fmaxf(rmax[ri], s);
                    }
            }
#pragma unroll
        for (int r = 0; r < 8; r++) {
            rmax[r] = fmaxf(rmax[r], __shfl_xor_sync(0xffffffffu, rmax[r], 1));
            rmax[r] = fmaxf(rmax[r], __shfl_xor_sync(0xffffffffu, rmax[r], 2));
        }
        if (tig == 0) {
#pragma unroll
            for (int ma = 0; ma < 4; ma++)
#pragma unroll
                for (int h = 0; h < 2; h++)
                    redm[(wq << 7) + (wm2 << 6) + (ma << 4) + g + (h << 3)] =
                        rmax[(ma << 1) + h];
        }
        __syncthreads();   // also: all warps done with K fragments

        float alpha[8], mnew[8], rsum[8];
#pragma unroll
        for (int ma = 0; ma < 4; ma++)
#pragma unroll
            for (int h = 0; h < 2; h++) {
                int row_l = (wm2 << 6) + (ma << 4) + g + (h << 3);
                int ri = (ma << 1) + h;
                float m4 = fmaxf(fmaxf(redm[row_l], redm[128 + row_l]),
                                 fmaxf(redm[256 + row_l], redm[384 + row_l]));
                mnew[ri] = fmaxf(m_i[ri], m4);
                alpha[ri] = __expf(m_i[ri] - mnew[ri]);
                m_i[ri] = mnew[ri];
                rsum[ri] = 0.f;
            }
        // p = exp(s - m) (fp32), store half into P (over K[buf])
        __half* Ph = (__half*)(smraw + TILE_B + (size_t)buf * (2 * TILE_B));
#pragma unroll
        for (int ma = 0; ma < 4; ma++)
#pragma unroll
            for (int h = 0; h < 2; h++) {
                int ri = (ma << 1) + h;
                int row_l = (wm2 << 6) + (ma << 4) + g + (h << 3);
                __half* prow = Ph + (size_t)row_l * 136 + (wq << 5);
#pragma unroll
                for (int na = 0; na < 4; na++) {
                    float p0 = __expf(sacc[ma][na][(h << 1) + 0] - mnew[ri]);
                    float p1 = __expf(sacc[ma][na][(h << 1) + 1] - mnew[ri]);
                    rsum[ri] += p0 + p1;
                    *(__half2*)(prow + (na << 3) + (tig << 1)) =
                        __floats2half2_rn(p0, p1);
                }
            }
#pragma unroll
        for (int r = 0; r < 8; r++) {
            rsum[r] += __shfl_xor_sync(0xffffffffu, rsum[r], 1);
            rsum[r] += __shfl_xor_sync(0xffffffffu, rsum[r], 2);
        }
        if (tig == 0) {
#pragma unroll
            for (int ma = 0; ma < 4; ma++)
#pragma unroll
                for (int h = 0; h < 2; h++)
                    reds[(wq << 7) + (wm2 << 6) + (ma << 4) + g + (h << 3)] =
                        rsum[(ma << 1) + h];
        }
        __syncthreads();   // P fully written, sums ready

#pragma unroll
        for (int ma = 0; ma < 4; ma++)
#pragma unroll
            for (int h = 0; h < 2; h++) {
                int row_l = (wm2 << 6) + (ma << 4) + g + (h << 3);
                int ri = (ma << 1) + h;
                float ls = reds[row_l] + reds[128 + row_l] +
                           reds[256 + row_l] + reds[384 + row_l];
                l_i[ri] = l_i[ri] * alpha[ri] + ls;
            }
#pragma unroll
        for (int ma = 0; ma < 4; ma++)
#pragma unroll
            for (int na = 0; na < 4; na++) {
                oacc[ma][na][0] *= alpha[(ma << 1)];
                oacc[ma][na][1] *= alpha[(ma << 1)];
                oacc[ma][na][2] *= alpha[(ma << 1) + 1];
                oacc[ma][na][3] *= alpha[(ma << 1) + 1];
            }

        // ---- O += P V : warp 64q x 32d, 8 k-steps of 16 keys ----
#pragma unroll
        for (int ks = 0; ks < 8; ks++) {
            uint32_t af[4][4], bf[4][2];
#pragma unroll
            for (int ma = 0; ma < 4; ma++)
                LDSM_X4(af[ma][0], af[ma][1], af[ma][2], af[ma][3],
                        k_sm + qa_lane + ma * (16 * ARB) + ks * 32);
#pragma unroll
            for (int np = 0; np < 2; np++)
                LDSM_X4T(bf[2 * np][0], bf[2 * np][1], bf[2 * np + 1][0],
                         bf[2 * np + 1][1],
                         v_sm + vb_rel + ks * (16 * ARB) + np * 32);
#pragma unroll
            for (int ma = 0; ma < 4; ma++)
#pragma unroll
                for (int na = 0; na < 4; na++)
                    mma_h(oacc[ma][na], af[ma], bf[na]);
        }
    }

    // ---- epilogue: normalize, half-round, write g_ATTh [B,T,C] ----
    int b  = bh >> 4;
    int hh = bh & 15;
#pragma unroll
    for (int ma = 0; ma < 4; ma++)
#pragma unroll
        for (int h = 0; h < 2; h++) {
            int row_l = (wm2 << 6) + (ma << 4) + g + (h << 3);
            int ri = (ma << 1) + h;
            int t = (qb << 7) + row_l;
            float inv = 1.f / l_i[ri];
            size_t base = ((size_t)b * T_ + t) * C_ + (hh << 7);
#pragma unroll
            for (int na = 0; na < 4; na++) {
                int d0 = (wq << 5) + (na << 3) + (tig << 1);
                __half2 v = __floats2half2_rn(oacc[ma][na][(h << 1) + 0] * inv,
                                              oacc[ma][na][(h << 1) + 1] * inv);
                *(__half2*)(g_ATTh + base + d0) = v;
            }
        }
}

// ---------------------------------------------------------------------------
extern "C" void kernel_launch(void* const* d_in, const int* in_sizes, int n_in,
                              void* d_out, int out_size)
{
    const float* x      = (const float*)d_in[0];
    const float* qkv_w  = (const float*)d_in[1];
    const float* qkv_b  = (const float*)d_in[2];
    const float* proj_w = (const float*)d_in[3];
    const float* proj_b = (const float*)d_in[4];
    float* out = (float*)d_out;

    cudaFuncSetAttribute(gemm_h, cudaFuncAttributeMaxDynamicSharedMemorySize,
                         GEMM_SMEM);
    cudaFuncSetAttribute(attn_h, cudaFuncAttributeMaxDynamicSharedMemorySize,
                         ATT_SMEM);

    // 0) fp16 conversion of all GEMM inputs (single launch)
    prep_all<<<(NX4 + NQ4 + NP4 + 255) / 256, 256>>>(
        (const float4*)x, (const float4*)qkv_w, (const float4*)proj_w);

    // 1) QKV projection: [8192,2048] @ [6144,2048]^T + b -> g_Qh/g_Kh/g_Vh
    gemm_h<<<dim3(48, 64), 256, GEMM_SMEM>>>(qkv_b, nullptr, 0);

    // 2) causal flash attention (fp16 mma) -> g_ATTh [B,T,C]
    attn_h<<<dim3(T_ / 128, B_ * H_), 256, ATT_SMEM>>>();

    // 3) output projection: g_ATTh @ proj_w^T + proj_b -> out (fp32)
    gemm_h<<<dim3(16, 64), 256, GEMM_SMEM>>>(proj_b, out, 1);
}